// round 1
// baseline (speedup 1.0000x reference)
#include <cuda_runtime.h>
#include <math.h>

// Problem constants (fixed shapes)
#define BB   4
#define TT   4096
#define DD   1024
#define MM   64
#define NN   128      // 2*M
#define BT   (BB*TT)  // 16384
#define DT_C 0.01f
#define CHUNK 64
#define NCH  (TT/CHUNK)   // 64

// ---------------- scratch (static __device__, no allocation) ----------------
__device__ float g_G[BT*256];        // raw projections [BT,256]
__device__ float g_ca[BT*MM];        // a = d*S
__device__ float g_cb[BT*MM];        // b = d*DT*A*S
__device__ float g_cc[BT*MM];        // c = d*DT*S
__device__ float g_F[BT*NN];         // F + bias
__device__ float g_xs[BT*NN];        // scan outputs
__device__ float g_P[BB*NCH*MM*4];   // chunk 2x2 products
__device__ float g_q[BB*NCH*MM*2];   // chunk offset vectors
__device__ float g_init[BB*NCH*MM*2];// per-chunk initial states

// ---------------- kernel 1: projection GEMM (NT), 64x64x16 tiles -----------
__global__ void proj_gemm(const float* __restrict__ u,
                          const float* __restrict__ Wo,
                          const float* __restrict__ Wz,
                          const float* __restrict__ WB)
{
    __shared__ float As[16][64];
    __shared__ float Bs[16][64];
    const int bm = blockIdx.y * 64;      // row tile over BT
    const int bn = blockIdx.x * 64;      // col tile over 256
    const int tid = threadIdx.x;         // 256 threads
    const int tx = tid & 15, ty = tid >> 4;

    float acc[4][4];
#pragma unroll
    for (int i = 0; i < 4; i++)
#pragma unroll
        for (int j = 0; j < 4; j++) acc[i][j] = 0.f;

    const int lrow = tid >> 2;           // 0..63
    const int lkc  = (tid & 3) * 4;      // 0,4,8,12

    for (int k0 = 0; k0 < DD; k0 += 16) {
        // A tile: u[bm+lrow][k0+lkc ..+3]
        {
            float4 v = *reinterpret_cast<const float4*>(
                &u[(size_t)(bm + lrow) * DD + k0 + lkc]);
            As[lkc+0][lrow] = v.x; As[lkc+1][lrow] = v.y;
            As[lkc+2][lrow] = v.z; As[lkc+3][lrow] = v.w;
        }
        // B tile: W[bn+lrow][k0+lkc ..+3], row select across the 3 weights
        {
            int j = bn + lrow;
            const float* wr = (j < 64) ? (Wo + (size_t)j * DD)
                            : (j < 128) ? (Wz + (size_t)(j - 64) * DD)
                                        : (WB + (size_t)(j - 128) * DD);
            float4 v = *reinterpret_cast<const float4*>(&wr[k0 + lkc]);
            Bs[lkc+0][lrow] = v.x; Bs[lkc+1][lrow] = v.y;
            Bs[lkc+2][lrow] = v.z; Bs[lkc+3][lrow] = v.w;
        }
        __syncthreads();
#pragma unroll
        for (int kk = 0; kk < 16; kk++) {
            float a[4], b[4];
#pragma unroll
            for (int i = 0; i < 4; i++) a[i] = As[kk][ty*4 + i];
#pragma unroll
            for (int j = 0; j < 4; j++) b[j] = Bs[kk][tx*4 + j];
#pragma unroll
            for (int i = 0; i < 4; i++)
#pragma unroll
                for (int j = 0; j < 4; j++) acc[i][j] = fmaf(a[i], b[j], acc[i][j]);
        }
        __syncthreads();
    }
#pragma unroll
    for (int i = 0; i < 4; i++)
#pragma unroll
        for (int j = 0; j < 4; j++)
            g_G[(size_t)(bm + ty*4 + i) * 256 + bn + tx*4 + j] = acc[i][j];
}

// ---------------- kernel 2: activations -> scan coefficients ----------------
__global__ void act_kernel(const float* __restrict__ bo,
                           const float* __restrict__ bz,
                           const float* __restrict__ bB)
{
    int idx = blockIdx.x * blockDim.x + threadIdx.x;  // over BT*NN
    if (idx >= BT * NN) return;
    int r = idx >> 7;        // /128
    int n = idx & 127;
    const float* Gr = &g_G[(size_t)r * 256];
    // F with bias
    g_F[(size_t)r * NN + n] = Gr[128 + n] + bB[n];
    if (n < MM) {
        int m = n;
        float vo = Gr[m] + bo[m];
        // stable softplus matching jax: max(x,0)+log1p(exp(-|x|))
        float sp = fmaxf(vo, 0.f) + log1pf(expf(-fabsf(vo)));
        float omega = fminf(fmaxf(sp, 1e-4f), 100.0f);
        float vz = Gr[64 + m] + bz[m];
        float zeta = 1.f / (1.f + expf(-vz));
        float d = 1.f - zeta;
        float A = omega * omega;
        float S = 1.f / (1.f + DT_C * DT_C * A);
        size_t o = (size_t)r * MM + m;
        g_ca[o] = d * S;
        g_cb[o] = d * DT_C * A * S;
        g_cc[o] = d * DT_C * S;
    }
}

// ---------------- kernel 3: scan phase 1 (chunk summaries) ------------------
__global__ void scan_phase1()
{
    int b = blockIdx.y, ch = blockIdx.x, m = threadIdx.x;  // 64 threads
    int t0 = ch * CHUNK;
    float P00 = 1.f, P01 = 0.f, P10 = 0.f, P11 = 1.f, qz = 0.f, qy = 0.f;
    for (int s = 0; s < CHUNK; s++) {
        size_t rt = (size_t)b * TT + t0 + s;
        float a  = g_ca[rt * MM + m];
        float bb = g_cb[rt * MM + m];
        float c  = g_cc[rt * MM + m];
        float Fz = g_F[rt * NN + m];
        float Fy = g_F[rt * NN + 64 + m];
        float n00 = a*P00 - bb*P10, n01 = a*P01 - bb*P11;
        float n10 = c*P00 + a*P10,  n11 = c*P01 + a*P11;
        float nqz = a*qz - bb*qy + Fz;
        float nqy = c*qz + a*qy + Fy;
        P00=n00; P01=n01; P10=n10; P11=n11; qz=nqz; qy=nqy;
    }
    size_t ci = ((size_t)b * NCH + ch) * MM + m;
    g_P[ci*4+0]=P00; g_P[ci*4+1]=P01; g_P[ci*4+2]=P10; g_P[ci*4+3]=P11;
    g_q[ci*2+0]=qz;  g_q[ci*2+1]=qy;
}

// ---------------- kernel 4: scan phase 2 (combine chunks, serial x64) -------
__global__ void scan_phase2()
{
    int tid = threadIdx.x;            // 256 = B*M
    int b = tid >> 6, m = tid & 63;
    float z = 0.f, y = 0.f;
    for (int ch = 0; ch < NCH; ch++) {
        size_t ci = ((size_t)b * NCH + ch) * MM + m;
        g_init[ci*2+0] = z; g_init[ci*2+1] = y;
        float P00=g_P[ci*4+0], P01=g_P[ci*4+1], P10=g_P[ci*4+2], P11=g_P[ci*4+3];
        float nz = P00*z + P01*y + g_q[ci*2+0];
        float ny = P10*z + P11*y + g_q[ci*2+1];
        z = nz; y = ny;
    }
}

// ---------------- kernel 5: scan phase 3 (replay with true init) ------------
__global__ void scan_phase3()
{
    int b = blockIdx.y, ch = blockIdx.x, m = threadIdx.x;
    int t0 = ch * CHUNK;
    size_t ci = ((size_t)b * NCH + ch) * MM + m;
    float z = g_init[ci*2+0], y = g_init[ci*2+1];
    for (int s = 0; s < CHUNK; s++) {
        size_t rt = (size_t)b * TT + t0 + s;
        float a  = g_ca[rt * MM + m];
        float bb = g_cb[rt * MM + m];
        float c  = g_cc[rt * MM + m];
        float Fz = g_F[rt * NN + m];
        float Fy = g_F[rt * NN + 64 + m];
        float nz = a*z - bb*y + Fz;
        float ny = c*z + a*y + Fy;
        z = nz; y = ny;
        g_xs[rt * NN + m]      = z;
        g_xs[rt * NN + 64 + m] = y;
    }
}

// ---------------- kernel 6: output GEMM: [xs|u] @ [C;Dmat]^T ----------------
__global__ void out_gemm(const float* __restrict__ u,
                         const float* __restrict__ Cm,
                         const float* __restrict__ Dm,
                         float* __restrict__ out)
{
    __shared__ float As[16][64];
    __shared__ float Bs[16][64];
    const int bm = blockIdx.y * 64;      // row tile over BT
    const int bn = blockIdx.x * 64;      // col tile over 1024
    const int tid = threadIdx.x;
    const int tx = tid & 15, ty = tid >> 4;

    float acc[4][4];
#pragma unroll
    for (int i = 0; i < 4; i++)
#pragma unroll
        for (int j = 0; j < 4; j++) acc[i][j] = 0.f;

    const int lrow = tid >> 2;
    const int lkc  = (tid & 3) * 4;

    for (int k0 = 0; k0 < NN + DD; k0 += 16) {
        bool first = (k0 < NN);
        {
            float4 v;
            if (first)
                v = *reinterpret_cast<const float4*>(
                    &g_xs[(size_t)(bm + lrow) * NN + k0 + lkc]);
            else
                v = *reinterpret_cast<const float4*>(
                    &u[(size_t)(bm + lrow) * DD + (k0 - NN) + lkc]);
            As[lkc+0][lrow] = v.x; As[lkc+1][lrow] = v.y;
            As[lkc+2][lrow] = v.z; As[lkc+3][lrow] = v.w;
        }
        {
            int d = bn + lrow;
            float4 v;
            if (first)
                v = *reinterpret_cast<const float4*>(
                    &Cm[(size_t)d * NN + k0 + lkc]);
            else
                v = *reinterpret_cast<const float4*>(
                    &Dm[(size_t)d * DD + (k0 - NN) + lkc]);
            Bs[lkc+0][lrow] = v.x; Bs[lkc+1][lrow] = v.y;
            Bs[lkc+2][lrow] = v.z; Bs[lkc+3][lrow] = v.w;
        }
        __syncthreads();
#pragma unroll
        for (int kk = 0; kk < 16; kk++) {
            float a[4], b[4];
#pragma unroll
            for (int i = 0; i < 4; i++) a[i] = As[kk][ty*4 + i];
#pragma unroll
            for (int j = 0; j < 4; j++) b[j] = Bs[kk][tx*4 + j];
#pragma unroll
            for (int i = 0; i < 4; i++)
#pragma unroll
                for (int j = 0; j < 4; j++) acc[i][j] = fmaf(a[i], b[j], acc[i][j]);
        }
        __syncthreads();
    }
#pragma unroll
    for (int i = 0; i < 4; i++)
#pragma unroll
        for (int j = 0; j < 4; j++)
            out[(size_t)(bm + ty*4 + i) * DD + bn + tx*4 + j] = acc[i][j];
}

// ---------------- launch ----------------------------------------------------
extern "C" void kernel_launch(void* const* d_in, const int* in_sizes, int n_in,
                              void* d_out, int out_size)
{
    const float* u   = (const float*)d_in[0];
    const float* Wo  = (const float*)d_in[1];
    const float* bo  = (const float*)d_in[2];
    const float* Wz  = (const float*)d_in[3];
    const float* bz  = (const float*)d_in[4];
    const float* WB  = (const float*)d_in[5];
    const float* bBv = (const float*)d_in[6];
    const float* Cm  = (const float*)d_in[7];
    const float* Dm  = (const float*)d_in[8];
    float* out = (float*)d_out;

    proj_gemm<<<dim3(256/64, BT/64), 256>>>(u, Wo, Wz, WB);
    act_kernel<<<(BT*NN + 255)/256, 256>>>(bo, bz, bBv);
    scan_phase1<<<dim3(NCH, BB), MM>>>();
    scan_phase2<<<1, BB*MM>>>();
    scan_phase3<<<dim3(NCH, BB), MM>>>();
    out_gemm<<<dim3(DD/64, BT/64), 256>>>(u, Cm, Dm, out);
}

// round 3
// speedup vs baseline: 2.8109x; 2.8109x over previous
#include <cuda_runtime.h>
#include <cuda_bf16.h>
#include <cstdint>
#include <math.h>

// ---------------- problem constants ----------------
#define BB   4
#define TT   4096
#define DD   1024
#define MM   64
#define NN   128
#define BT   (BB*TT)     // 16384
#define DT_C 0.01f
#define CHUNK 64
#define NCH  (TT/CHUNK)  // 64
#define KX   1152        // concat K for out gemm: [xs(128) | u(1024)]

// ---------------- portable PTX helpers (sm_80+ ISA only) ----------------
__device__ __forceinline__ uint32_t smem_to_u32(const void* p) {
    uint32_t a;
    asm("{ .reg .u64 t; cvta.to.shared.u64 t, %1; cvt.u32.u64 %0, t; }" : "=r"(a) : "l"(p));
    return a;
}
#define CP_ASYNC16(SM, GM) \
    asm volatile("cp.async.cg.shared.global [%0], [%1], 16;" :: "r"(SM), "l"(GM) : "memory")
#define CP_COMMIT() asm volatile("cp.async.commit_group;" ::: "memory")
#define CP_WAIT1()  asm volatile("cp.async.wait_group 1;" ::: "memory")
#define CP_WAIT0()  asm volatile("cp.async.wait_group 0;" ::: "memory")
#define LDSM_X4(R0,R1,R2,R3, ADDR) \
    asm volatile("ldmatrix.sync.aligned.m8n8.x4.shared.b16 {%0,%1,%2,%3}, [%4];" \
        : "=r"(R0),"=r"(R1),"=r"(R2),"=r"(R3) : "r"(ADDR))
#define MMA_BF16(D, A, B) \
    asm volatile("mma.sync.aligned.m16n8k16.row.col.f32.bf16.bf16.f32 " \
        "{%0,%1,%2,%3}, {%4,%5,%6,%7}, {%8,%9}, {%0,%1,%2,%3};" \
        : "+f"((D)[0]), "+f"((D)[1]), "+f"((D)[2]), "+f"((D)[3]) \
        : "r"((A)[0]), "r"((A)[1]), "r"((A)[2]), "r"((A)[3]), "r"((B)[0]), "r"((B)[1]))

// ---------------- scratch (static device, no allocation) ----------------
__device__ __align__(16) __nv_bfloat16 g_Xh[(size_t)BT*KX];   // [xs | u] hi
__device__ __align__(16) __nv_bfloat16 g_Xl[(size_t)BT*KX];   // [xs | u] lo
__device__ __align__(16) __nv_bfloat16 g_Wph[256*DD];         // proj W hi [256,1024]
__device__ __align__(16) __nv_bfloat16 g_Wpl[256*DD];
__device__ __align__(16) __nv_bfloat16 g_Wch[(size_t)DD*KX];  // [C|D] hi [1024,1152]
__device__ __align__(16) __nv_bfloat16 g_Wcl[(size_t)DD*KX];
__device__ float g_G[(size_t)BT*256];
__device__ float g_ca[(size_t)BT*MM];
__device__ float g_cb[(size_t)BT*MM];
__device__ float g_cc[(size_t)BT*MM];
__device__ float g_F[(size_t)BT*NN];
__device__ float g_P00[BB*NCH*MM], g_P01[BB*NCH*MM], g_P10[BB*NCH*MM], g_P11[BB*NCH*MM];
__device__ float g_qz[BB*NCH*MM],  g_qy[BB*NCH*MM];
__device__ float g_iz[BB*NCH*MM],  g_iy[BB*NCH*MM];

__device__ __forceinline__ void split2(float x, __nv_bfloat16& h, __nv_bfloat16& l) {
    h = __float2bfloat16(x);
    l = __float2bfloat16(x - __bfloat162float(h));
}

// ---------------- conversion kernels ----------------
__global__ void conv_u(const float* __restrict__ u) {
    int i = blockIdx.x * blockDim.x + threadIdx.x;      // over BT*256 float4s
    if (i >= BT * 256) return;
    int row = i >> 8, c4 = i & 255;
    float4 v = reinterpret_cast<const float4*>(u)[i];
    union { __nv_bfloat16 b[4]; uint2 u2; } ph, pl;
    split2(v.x, ph.b[0], pl.b[0]); split2(v.y, ph.b[1], pl.b[1]);
    split2(v.z, ph.b[2], pl.b[2]); split2(v.w, ph.b[3], pl.b[3]);
    size_t o = (size_t)row * KX + 128 + c4 * 4;
    *reinterpret_cast<uint2*>(&g_Xh[o]) = ph.u2;
    *reinterpret_cast<uint2*>(&g_Xl[o]) = pl.u2;
}

__global__ void conv_wp(const float* __restrict__ Wo, const float* __restrict__ Wz,
                        const float* __restrict__ WB) {
    int i = blockIdx.x * blockDim.x + threadIdx.x;      // over 256*256 float4s
    if (i >= 256 * 256) return;
    int row = i >> 8, c4 = i & 255;
    const float* src = (row < 64)  ? (Wo + (size_t)row * DD)
                     : (row < 128) ? (Wz + (size_t)(row - 64) * DD)
                                   : (WB + (size_t)(row - 128) * DD);
    float4 v = *reinterpret_cast<const float4*>(src + c4 * 4);
    union { __nv_bfloat16 b[4]; uint2 u2; } ph, pl;
    split2(v.x, ph.b[0], pl.b[0]); split2(v.y, ph.b[1], pl.b[1]);
    split2(v.z, ph.b[2], pl.b[2]); split2(v.w, ph.b[3], pl.b[3]);
    size_t o = (size_t)row * DD + c4 * 4;
    *reinterpret_cast<uint2*>(&g_Wph[o]) = ph.u2;
    *reinterpret_cast<uint2*>(&g_Wpl[o]) = pl.u2;
}

__global__ void conv_wc(const float* __restrict__ Cm, const float* __restrict__ Dm) {
    int i = blockIdx.x * blockDim.x + threadIdx.x;      // over 1024*288 float4s
    if (i >= 1024 * 288) return;
    int row = i / 288, c4 = i % 288;
    int k = c4 * 4;
    float4 v = (k < 128)
        ? *reinterpret_cast<const float4*>(&Cm[(size_t)row * NN + k])
        : *reinterpret_cast<const float4*>(&Dm[(size_t)row * DD + (k - 128)]);
    union { __nv_bfloat16 b[4]; uint2 u2; } ph, pl;
    split2(v.x, ph.b[0], pl.b[0]); split2(v.y, ph.b[1], pl.b[1]);
    split2(v.z, ph.b[2], pl.b[2]); split2(v.w, ph.b[3], pl.b[3]);
    size_t o = (size_t)row * KX + k;
    *reinterpret_cast<uint2*>(&g_Wch[o]) = ph.u2;
    *reinterpret_cast<uint2*>(&g_Wcl[o]) = pl.u2;
}

// ---------------- split-bf16 warp-MMA GEMM ----------------
// C[M,N] = Ah*Bh^T + Al*Bh^T + Ah*Bl^T  (fp32 accum)
// A: [M,K] row-major, B: [N,K] row-major. CTA tile 128x128, K-chunk 32.
// smem tile: 128 rows x 32 bf16, padded stride 40 bf16 (80B) -> conflict-free ldmatrix.
#define TILEB  10240          // 128*80 bytes
#define STAGEB (4*TILEB)      // Ah, Al, Bh, Bl
#define GEMM_SMEM (2*STAGEB)  // 81920

__global__ void __launch_bounds__(256)
gemm_mma(const __nv_bfloat16* __restrict__ Ah, const __nv_bfloat16* __restrict__ Al, int lda,
         const __nv_bfloat16* __restrict__ Bh, const __nv_bfloat16* __restrict__ Bl, int ldb,
         float* __restrict__ Cout, int ldc, int K)
{
    extern __shared__ char smc[];
    const uint32_t sb = smem_to_u32(smc);
    const int tid = threadIdx.x;
    const int wid = tid >> 5, lane = tid & 31;
    const int warpM = wid & 3, warpN = wid >> 2;
    const int rowBase = blockIdx.y * 128;
    const int colBase = blockIdx.x * 128;

    const __nv_bfloat16* gbase[4] = {Ah, Al, Bh, Bl};
    const int ldv[4] = {lda, lda, ldb, ldb};
    const int rb[4]  = {rowBase, rowBase, colBase, colBase};

    auto load_stage = [&](int stage, int k0) {
#pragma unroll
        for (int i = 0; i < 8; i++) {
            int idx = i * 256 + tid;           // 0..2047
            int tile = idx >> 9;
            int e = idx & 511;
            int r = e >> 2, j = e & 3;
            uint32_t so = sb + stage * STAGEB + tile * TILEB + r * 80 + j * 16;
            const __nv_bfloat16* g = gbase[tile]
                + (size_t)(rb[tile] + r) * ldv[tile] + k0 + j * 8;
            CP_ASYNC16(so, g);
        }
        CP_COMMIT();
    };

    float acc[2][8][4];
#pragma unroll
    for (int a = 0; a < 2; a++)
#pragma unroll
        for (int b = 0; b < 8; b++)
#pragma unroll
            for (int c = 0; c < 4; c++) acc[a][b][c] = 0.f;

    // lane-invariant ldmatrix address parts
    const uint32_t aRowOff = (uint32_t)(lane & 15) * 80 + (uint32_t)(lane >> 4) * 16;
    const uint32_t bRowOff = (uint32_t)((lane & 7) + ((lane >> 4) & 1) * 8) * 80
                           + (uint32_t)((lane >> 3) & 1) * 16;

    const int nch = K / 32;
    load_stage(0, 0);
    for (int c = 0; c < nch; c++) {
        if (c + 1 < nch) { load_stage((c + 1) & 1, (c + 1) * 32); CP_WAIT1(); }
        else             { CP_WAIT0(); }
        __syncthreads();
        const uint32_t st = sb + (c & 1) * STAGEB;
#pragma unroll
        for (int k16 = 0; k16 < 2; k16++) {
            const uint32_t kb = (uint32_t)k16 * 32;
            uint32_t ah[2][4], al[2][4], bh[8][2], bl[8][2];
#pragma unroll
            for (int mf = 0; mf < 2; mf++) {
                uint32_t base = st + (uint32_t)(warpM * 32 + mf * 16) * 80 + kb + aRowOff;
                LDSM_X4(ah[mf][0], ah[mf][1], ah[mf][2], ah[mf][3], base);            // Ah tile
                LDSM_X4(al[mf][0], al[mf][1], al[mf][2], al[mf][3], base + TILEB);    // Al tile
            }
#pragma unroll
            for (int p = 0; p < 4; p++) {
                uint32_t base = st + (uint32_t)(warpN * 64 + p * 16) * 80 + kb + bRowOff;
                uint32_t r0, r1, r2, r3;
                LDSM_X4(r0, r1, r2, r3, base + 2 * TILEB);                            // Bh tile
                bh[2*p][0] = r0; bh[2*p][1] = r1; bh[2*p+1][0] = r2; bh[2*p+1][1] = r3;
                LDSM_X4(r0, r1, r2, r3, base + 3 * TILEB);                            // Bl tile
                bl[2*p][0] = r0; bl[2*p][1] = r1; bl[2*p+1][0] = r2; bl[2*p+1][1] = r3;
            }
#pragma unroll
            for (int mf = 0; mf < 2; mf++)
#pragma unroll
                for (int nf = 0; nf < 8; nf++) MMA_BF16(acc[mf][nf], ah[mf], bh[nf]);
#pragma unroll
            for (int mf = 0; mf < 2; mf++)
#pragma unroll
                for (int nf = 0; nf < 8; nf++) MMA_BF16(acc[mf][nf], al[mf], bh[nf]);
#pragma unroll
            for (int mf = 0; mf < 2; mf++)
#pragma unroll
                for (int nf = 0; nf < 8; nf++) MMA_BF16(acc[mf][nf], ah[mf], bl[nf]);
        }
        __syncthreads();
    }

    // epilogue: direct fp32 stores
    const int row0 = rowBase + warpM * 32 + (lane >> 2);
    const int col0 = colBase + warpN * 64 + (lane & 3) * 2;
#pragma unroll
    for (int mf = 0; mf < 2; mf++)
#pragma unroll
        for (int nf = 0; nf < 8; nf++) {
            int r = row0 + mf * 16, cc = col0 + nf * 8;
            float2 v0 = make_float2(acc[mf][nf][0], acc[mf][nf][1]);
            float2 v1 = make_float2(acc[mf][nf][2], acc[mf][nf][3]);
            *reinterpret_cast<float2*>(&Cout[(size_t)r * ldc + cc]) = v0;
            *reinterpret_cast<float2*>(&Cout[(size_t)(r + 8) * ldc + cc]) = v1;
        }
}

// ---------------- activations -> scan coefficients ----------------
__global__ void act_kernel(const float* __restrict__ bo, const float* __restrict__ bz,
                           const float* __restrict__ bB)
{
    int idx = blockIdx.x * blockDim.x + threadIdx.x;
    if (idx >= BT * NN) return;
    int r = idx >> 7, n = idx & 127;
    const float* Gr = &g_G[(size_t)r * 256];
    g_F[(size_t)r * NN + n] = Gr[128 + n] + bB[n];
    if (n < MM) {
        int m = n;
        float vo = Gr[m] + bo[m];
        float sp = fmaxf(vo, 0.f) + log1pf(expf(-fabsf(vo)));
        float omega = fminf(fmaxf(sp, 1e-4f), 100.0f);
        float vz = Gr[64 + m] + bz[m];
        float zeta = 1.f / (1.f + expf(-vz));
        float d = 1.f - zeta;
        float A = omega * omega;
        float S = 1.f / (1.f + DT_C * DT_C * A);
        size_t o = (size_t)r * MM + m;
        g_ca[o] = d * S;
        g_cb[o] = d * DT_C * A * S;
        g_cc[o] = d * DT_C * S;
    }
}

// ---------------- scan phase 1: chunk summaries ----------------
__global__ void scan_phase1()
{
    int b = blockIdx.y, ch = blockIdx.x, m = threadIdx.x;
    int t0 = ch * CHUNK;
    float P00 = 1.f, P01 = 0.f, P10 = 0.f, P11 = 1.f, qz = 0.f, qy = 0.f;
#pragma unroll 4
    for (int s = 0; s < CHUNK; s++) {
        size_t rt = (size_t)b * TT + t0 + s;
        float a  = g_ca[rt * MM + m];
        float bb = g_cb[rt * MM + m];
        float cc = g_cc[rt * MM + m];
        float Fz = g_F[rt * NN + m];
        float Fy = g_F[rt * NN + 64 + m];
        float n00 = a*P00 - bb*P10, n01 = a*P01 - bb*P11;
        float n10 = cc*P00 + a*P10, n11 = cc*P01 + a*P11;
        float nqz = a*qz - bb*qy + Fz;
        float nqy = cc*qz + a*qy + Fy;
        P00=n00; P01=n01; P10=n10; P11=n11; qz=nqz; qy=nqy;
    }
    int ci = (b * NCH + ch) * MM + m;
    g_P00[ci]=P00; g_P01[ci]=P01; g_P10[ci]=P10; g_P11[ci]=P11;
    g_qz[ci]=qz;   g_qy[ci]=qy;
}

// ---------------- scan phase 2: combine (batched prefetch, MLP) ----------
__global__ void scan_phase2()
{
    int tid = threadIdx.x;        // 256 = B*M
    int b = tid >> 6, m = tid & 63;
    float z = 0.f, y = 0.f;
    for (int g = 0; g < NCH; g += 8) {
        float p00[8], p01[8], p10[8], p11[8], vz[8], vy[8];
#pragma unroll
        for (int j = 0; j < 8; j++) {
            int ci = (b * NCH + g + j) * MM + m;
            p00[j] = g_P00[ci]; p01[j] = g_P01[ci];
            p10[j] = g_P10[ci]; p11[j] = g_P11[ci];
            vz[j]  = g_qz[ci];  vy[j]  = g_qy[ci];
        }
#pragma unroll
        for (int j = 0; j < 8; j++) {
            int ci = (b * NCH + g + j) * MM + m;
            g_iz[ci] = z; g_iy[ci] = y;
            float nz = p00[j]*z + p01[j]*y + vz[j];
            float ny = p10[j]*z + p11[j]*y + vy[j];
            z = nz; y = ny;
        }
    }
}

// ---------------- scan phase 3: replay, write bf16 splits into X ----------
__global__ void scan_phase3()
{
    int b = blockIdx.y, ch = blockIdx.x, m = threadIdx.x;
    int t0 = ch * CHUNK;
    int ci = (b * NCH + ch) * MM + m;
    float z = g_iz[ci], y = g_iy[ci];
#pragma unroll 4
    for (int s = 0; s < CHUNK; s++) {
        size_t rt = (size_t)b * TT + t0 + s;
        float a  = g_ca[rt * MM + m];
        float bb = g_cb[rt * MM + m];
        float cc = g_cc[rt * MM + m];
        float Fz = g_F[rt * NN + m];
        float Fy = g_F[rt * NN + 64 + m];
        float nz = a*z - bb*y + Fz;
        float ny = cc*z + a*y + Fy;
        z = nz; y = ny;
        __nv_bfloat16 h, l;
        size_t xo = rt * KX;
        split2(z, h, l); g_Xh[xo + m] = h;      g_Xl[xo + m] = l;
        split2(y, h, l); g_Xh[xo + 64 + m] = h; g_Xl[xo + 64 + m] = l;
    }
}

// ---------------- launch ----------------
extern "C" void kernel_launch(void* const* d_in, const int* in_sizes, int n_in,
                              void* d_out, int out_size)
{
    const float* u   = (const float*)d_in[0];
    const float* Wo  = (const float*)d_in[1];
    const float* bo  = (const float*)d_in[2];
    const float* Wz  = (const float*)d_in[3];
    const float* bz  = (const float*)d_in[4];
    const float* WB  = (const float*)d_in[5];
    const float* bBv = (const float*)d_in[6];
    const float* Cm  = (const float*)d_in[7];
    const float* Dm  = (const float*)d_in[8];
    float* out = (float*)d_out;

    static int configured = 0;
    if (!configured) {
        cudaFuncSetAttribute(gemm_mma, cudaFuncAttributeMaxDynamicSharedMemorySize, GEMM_SMEM);
        configured = 1;
    }

    __nv_bfloat16 *Xh, *Xl, *Wph, *Wpl, *Wch, *Wcl; float* G;
    cudaGetSymbolAddress((void**)&Xh,  g_Xh);
    cudaGetSymbolAddress((void**)&Xl,  g_Xl);
    cudaGetSymbolAddress((void**)&Wph, g_Wph);
    cudaGetSymbolAddress((void**)&Wpl, g_Wpl);
    cudaGetSymbolAddress((void**)&Wch, g_Wch);
    cudaGetSymbolAddress((void**)&Wcl, g_Wcl);
    cudaGetSymbolAddress((void**)&G,   g_G);

    // 1. fp32 -> split bf16 conversions
    conv_u <<<(BT * 256 + 255) / 256, 256>>>(u);
    conv_wp<<<(256 * 256 + 255) / 256, 256>>>(Wo, Wz, WB);
    conv_wc<<<(1024 * 288 + 255) / 256, 256>>>(Cm, Dm);

    // 2. projection GEMM: G[BT,256] = u_splits (K=1024) @ Wp^T
    gemm_mma<<<dim3(256 / 128, BT / 128), 256, GEMM_SMEM>>>(
        Xh + 128, Xl + 128, KX, Wph, Wpl, DD, G, 256, DD);

    // 3. activations + chunked parallel scan
    act_kernel<<<(BT * NN + 255) / 256, 256>>>(bo, bz, bBv);
    scan_phase1<<<dim3(NCH, BB), MM>>>();
    scan_phase2<<<1, BB * MM>>>();
    scan_phase3<<<dim3(NCH, BB), MM>>>();

    // 4. output GEMM: out[BT,1024] = X (K=1152) @ [C|D]^T
    gemm_mma<<<dim3(DD / 128, BT / 128), 256, GEMM_SMEM>>>(
        Xh, Xl, KX, Wch, Wcl, KX, out, DD, KX);
}

// round 4
// speedup vs baseline: 3.2272x; 1.1481x over previous
#include <cuda_runtime.h>
#include <cuda_bf16.h>
#include <cstdint>
#include <math.h>

// ---------------- problem constants ----------------
#define BB   4
#define TT   4096
#define DD   1024
#define MM   64
#define NN   128
#define BT   (BB*TT)     // 16384
#define DT_C 0.01f
#define CHUNK 64
#define NCH  (TT/CHUNK)  // 64
#define KX   1152        // concat K for out gemm: [xs(128) | u(1024)]

// ---------------- portable PTX helpers (sm_80+ ISA only) ----------------
__device__ __forceinline__ uint32_t smem_to_u32(const void* p) {
    uint32_t a;
    asm("{ .reg .u64 t; cvta.to.shared.u64 t, %1; cvt.u32.u64 %0, t; }" : "=r"(a) : "l"(p));
    return a;
}
#define CP_ASYNC16(SM, GM) \
    asm volatile("cp.async.cg.shared.global [%0], [%1], 16;" :: "r"(SM), "l"(GM) : "memory")
#define CP_COMMIT() asm volatile("cp.async.commit_group;" ::: "memory")
#define CP_WAIT1()  asm volatile("cp.async.wait_group 1;" ::: "memory")
#define CP_WAIT0()  asm volatile("cp.async.wait_group 0;" ::: "memory")
#define LDSM_X4(R0,R1,R2,R3, ADDR) \
    asm volatile("ldmatrix.sync.aligned.m8n8.x4.shared.b16 {%0,%1,%2,%3}, [%4];" \
        : "=r"(R0),"=r"(R1),"=r"(R2),"=r"(R3) : "r"(ADDR))
#define MMA_BF16(D, A, B) \
    asm volatile("mma.sync.aligned.m16n8k16.row.col.f32.bf16.bf16.f32 " \
        "{%0,%1,%2,%3}, {%4,%5,%6,%7}, {%8,%9}, {%0,%1,%2,%3};" \
        : "+f"((D)[0]), "+f"((D)[1]), "+f"((D)[2]), "+f"((D)[3]) \
        : "r"((A)[0]), "r"((A)[1]), "r"((A)[2]), "r"((A)[3]), "r"((B)[0]), "r"((B)[1]))

// ---------------- scratch (static device, no allocation) ----------------
__device__ __align__(16) __nv_bfloat16 g_Xh[(size_t)BT*KX];   // [xs | u] hi
__device__ __align__(16) __nv_bfloat16 g_Xl[(size_t)BT*KX];   // [xs | u] lo
__device__ __align__(16) __nv_bfloat16 g_Wph[256*DD];         // proj W hi [256,1024]
__device__ __align__(16) __nv_bfloat16 g_Wpl[256*DD];
__device__ __align__(16) __nv_bfloat16 g_Wch[(size_t)DD*KX];  // [C|D] hi [1024,1152]
__device__ __align__(16) __nv_bfloat16 g_Wcl[(size_t)DD*KX];
__device__ float g_G[(size_t)BT*256];
__device__ float g_P00[BB*NCH*MM], g_P01[BB*NCH*MM], g_P10[BB*NCH*MM], g_P11[BB*NCH*MM];
__device__ float g_qz[BB*NCH*MM],  g_qy[BB*NCH*MM];
__device__ float g_iz[BB*NCH*MM],  g_iy[BB*NCH*MM];

__device__ __forceinline__ void split2(float x, __nv_bfloat16& h, __nv_bfloat16& l) {
    h = __float2bfloat16(x);
    l = __float2bfloat16(x - __bfloat162float(h));
}

// shared coefficient computation: from raw projections + biases
__device__ __forceinline__ void coeffs(float go, float gz, float bom, float bzm,
                                       float& a, float& bb, float& cc)
{
    float vo = go + bom;
    float sp = fmaxf(vo, 0.f) + log1pf(expf(-fabsf(vo)));
    float omega = fminf(fmaxf(sp, 1e-4f), 100.0f);
    float vz = gz + bzm;
    float zeta = 1.f / (1.f + expf(-vz));
    float d = 1.f - zeta;
    float A = omega * omega;
    float S = 1.f / (1.f + DT_C * DT_C * A);
    a  = d * S;
    bb = d * DT_C * A * S;
    cc = d * DT_C * S;
}

// ---------------- conversion kernels ----------------
__global__ void conv_u(const float* __restrict__ u) {
    int i = blockIdx.x * blockDim.x + threadIdx.x;      // over BT*256 float4s
    if (i >= BT * 256) return;
    int row = i >> 8, c4 = i & 255;
    float4 v = reinterpret_cast<const float4*>(u)[i];
    union { __nv_bfloat16 b[4]; uint2 u2; } ph, pl;
    split2(v.x, ph.b[0], pl.b[0]); split2(v.y, ph.b[1], pl.b[1]);
    split2(v.z, ph.b[2], pl.b[2]); split2(v.w, ph.b[3], pl.b[3]);
    size_t o = (size_t)row * KX + 128 + c4 * 4;
    *reinterpret_cast<uint2*>(&g_Xh[o]) = ph.u2;
    *reinterpret_cast<uint2*>(&g_Xl[o]) = pl.u2;
}

__global__ void conv_wp(const float* __restrict__ Wo, const float* __restrict__ Wz,
                        const float* __restrict__ WB) {
    int i = blockIdx.x * blockDim.x + threadIdx.x;      // over 256*256 float4s
    if (i >= 256 * 256) return;
    int row = i >> 8, c4 = i & 255;
    const float* src = (row < 64)  ? (Wo + (size_t)row * DD)
                     : (row < 128) ? (Wz + (size_t)(row - 64) * DD)
                                   : (WB + (size_t)(row - 128) * DD);
    float4 v = *reinterpret_cast<const float4*>(src + c4 * 4);
    union { __nv_bfloat16 b[4]; uint2 u2; } ph, pl;
    split2(v.x, ph.b[0], pl.b[0]); split2(v.y, ph.b[1], pl.b[1]);
    split2(v.z, ph.b[2], pl.b[2]); split2(v.w, ph.b[3], pl.b[3]);
    size_t o = (size_t)row * DD + c4 * 4;
    *reinterpret_cast<uint2*>(&g_Wph[o]) = ph.u2;
    *reinterpret_cast<uint2*>(&g_Wpl[o]) = pl.u2;
}

__global__ void conv_wc(const float* __restrict__ Cm, const float* __restrict__ Dm) {
    int i = blockIdx.x * blockDim.x + threadIdx.x;      // over 1024*288 float4s
    if (i >= 1024 * 288) return;
    int row = i / 288, c4 = i % 288;
    int k = c4 * 4;
    float4 v = (k < 128)
        ? *reinterpret_cast<const float4*>(&Cm[(size_t)row * NN + k])
        : *reinterpret_cast<const float4*>(&Dm[(size_t)row * DD + (k - 128)]);
    union { __nv_bfloat16 b[4]; uint2 u2; } ph, pl;
    split2(v.x, ph.b[0], pl.b[0]); split2(v.y, ph.b[1], pl.b[1]);
    split2(v.z, ph.b[2], pl.b[2]); split2(v.w, ph.b[3], pl.b[3]);
    size_t o = (size_t)row * KX + k;
    *reinterpret_cast<uint2*>(&g_Wch[o]) = ph.u2;
    *reinterpret_cast<uint2*>(&g_Wcl[o]) = pl.u2;
}

// ---------------- split-bf16 warp-MMA GEMM ----------------
// C = Ah*Bh^T + Al*Bh^T + Ah*Bl^T (fp32 accum). CTA tile 128x128, K-chunk 32.
// smem: 128 rows x 32 bf16, padded stride 40 bf16 (80B), double buffered.
#define TILEB  10240          // 128*80 bytes
#define STAGEB (4*TILEB)      // Ah, Al, Bh, Bl
#define GEMM_SMEM (2*STAGEB)  // 81920

__global__ void __launch_bounds__(256, 2)
gemm_mma(const __nv_bfloat16* __restrict__ Ah, const __nv_bfloat16* __restrict__ Al, int lda,
         const __nv_bfloat16* __restrict__ Bh, const __nv_bfloat16* __restrict__ Bl, int ldb,
         float* __restrict__ Cout, int ldc, int K)
{
    extern __shared__ char smc[];
    const uint32_t sb = smem_to_u32(smc);
    const int tid = threadIdx.x;
    const int wid = tid >> 5, lane = tid & 31;
    const int warpM = wid & 3, warpN = wid >> 2;
    const int rowBase = blockIdx.y * 128;
    const int colBase = blockIdx.x * 128;

    const __nv_bfloat16* gbase[4] = {Ah, Al, Bh, Bl};
    const int ldv[4] = {lda, lda, ldb, ldb};
    const int rb[4]  = {rowBase, rowBase, colBase, colBase};

    auto load_stage = [&](int stage, int k0) {
#pragma unroll
        for (int i = 0; i < 8; i++) {
            int idx = i * 256 + tid;           // 0..2047
            int tile = idx >> 9;
            int e = idx & 511;
            int r = e >> 2, j = e & 3;
            uint32_t so = sb + stage * STAGEB + tile * TILEB + r * 80 + j * 16;
            const __nv_bfloat16* g = gbase[tile]
                + (size_t)(rb[tile] + r) * ldv[tile] + k0 + j * 8;
            CP_ASYNC16(so, g);
        }
        CP_COMMIT();
    };

    float acc[2][8][4];
#pragma unroll
    for (int a = 0; a < 2; a++)
#pragma unroll
        for (int b = 0; b < 8; b++)
#pragma unroll
            for (int c = 0; c < 4; c++) acc[a][b][c] = 0.f;

    const uint32_t aRowOff = (uint32_t)(lane & 15) * 80 + (uint32_t)(lane >> 4) * 16;
    const uint32_t bRowOff = (uint32_t)((lane & 7) + ((lane >> 4) & 1) * 8) * 80
                           + (uint32_t)((lane >> 3) & 1) * 16;

    const int nch = K / 32;
    load_stage(0, 0);
    for (int c = 0; c < nch; c++) {
        if (c + 1 < nch) { load_stage((c + 1) & 1, (c + 1) * 32); CP_WAIT1(); }
        else             { CP_WAIT0(); }
        __syncthreads();
        const uint32_t st = sb + (c & 1) * STAGEB;
#pragma unroll
        for (int k16 = 0; k16 < 2; k16++) {
            const uint32_t kb = (uint32_t)k16 * 32;
            uint32_t ah[2][4], al[2][4];
#pragma unroll
            for (int mf = 0; mf < 2; mf++) {
                uint32_t base = st + (uint32_t)(warpM * 32 + mf * 16) * 80 + kb + aRowOff;
                LDSM_X4(ah[mf][0], ah[mf][1], ah[mf][2], ah[mf][3], base);
                LDSM_X4(al[mf][0], al[mf][1], al[mf][2], al[mf][3], base + TILEB);
            }
            // process B in pairs of nf (keeps live registers low -> 2 CTAs/SM)
#pragma unroll
            for (int p = 0; p < 4; p++) {
                uint32_t base = st + (uint32_t)(warpN * 64 + p * 16) * 80 + kb + bRowOff;
                uint32_t bh[2][2], bl[2][2];
                uint32_t r0, r1, r2, r3;
                LDSM_X4(r0, r1, r2, r3, base + 2 * TILEB);
                bh[0][0] = r0; bh[0][1] = r1; bh[1][0] = r2; bh[1][1] = r3;
                LDSM_X4(r0, r1, r2, r3, base + 3 * TILEB);
                bl[0][0] = r0; bl[0][1] = r1; bl[1][0] = r2; bl[1][1] = r3;
#pragma unroll
                for (int h = 0; h < 2; h++) {
                    int nf = 2 * p + h;
#pragma unroll
                    for (int mf = 0; mf < 2; mf++) {
                        MMA_BF16(acc[mf][nf], ah[mf], bh[h]);
                        MMA_BF16(acc[mf][nf], al[mf], bh[h]);
                        MMA_BF16(acc[mf][nf], ah[mf], bl[h]);
                    }
                }
            }
        }
        __syncthreads();
    }

    const int row0 = rowBase + warpM * 32 + (lane >> 2);
    const int col0 = colBase + warpN * 64 + (lane & 3) * 2;
#pragma unroll
    for (int mf = 0; mf < 2; mf++)
#pragma unroll
        for (int nf = 0; nf < 8; nf++) {
            int r = row0 + mf * 16, cc = col0 + nf * 8;
            float2 v0 = make_float2(acc[mf][nf][0], acc[mf][nf][1]);
            float2 v1 = make_float2(acc[mf][nf][2], acc[mf][nf][3]);
            *reinterpret_cast<float2*>(&Cout[(size_t)r * ldc + cc]) = v0;
            *reinterpret_cast<float2*>(&Cout[(size_t)(r + 8) * ldc + cc]) = v1;
        }
}

// ---------------- scan phase 1 (fused act): chunk summaries ----------------
__global__ void scan_phase1(const float* __restrict__ bo, const float* __restrict__ bz,
                            const float* __restrict__ bB)
{
    int b = blockIdx.y, ch = blockIdx.x, m = threadIdx.x;
    const float bom = bo[m], bzm = bz[m], bBz = bB[m], bBy = bB[64 + m];
    const float* Gp = g_G + ((size_t)b * TT + ch * CHUNK) * 256;
    float P00 = 1.f, P01 = 0.f, P10 = 0.f, P11 = 1.f, qz = 0.f, qy = 0.f;
#pragma unroll 4
    for (int s = 0; s < CHUNK; s++) {
        const float* Gr = Gp + (size_t)s * 256;
        float go = Gr[m], gz = Gr[64 + m];
        float Fz = Gr[128 + m] + bBz;
        float Fy = Gr[192 + m] + bBy;
        float a, bb, cc;
        coeffs(go, gz, bom, bzm, a, bb, cc);
        float n00 = a*P00 - bb*P10, n01 = a*P01 - bb*P11;
        float n10 = cc*P00 + a*P10, n11 = cc*P01 + a*P11;
        float nqz = a*qz - bb*qy + Fz;
        float nqy = cc*qz + a*qy + Fy;
        P00=n00; P01=n01; P10=n10; P11=n11; qz=nqz; qy=nqy;
    }
    int ci = (b * NCH + ch) * MM + m;
    g_P00[ci]=P00; g_P01[ci]=P01; g_P10[ci]=P10; g_P11[ci]=P11;
    g_qz[ci]=qz;   g_qy[ci]=qy;
}

// ---------------- scan phase 2: combine (batched prefetch) ----------------
__global__ void scan_phase2()
{
    int tid = threadIdx.x;        // 256 = B*M
    int b = tid >> 6, m = tid & 63;
    float z = 0.f, y = 0.f;
    for (int g = 0; g < NCH; g += 8) {
        float p00[8], p01[8], p10[8], p11[8], vz[8], vy[8];
#pragma unroll
        for (int j = 0; j < 8; j++) {
            int ci = (b * NCH + g + j) * MM + m;
            p00[j] = g_P00[ci]; p01[j] = g_P01[ci];
            p10[j] = g_P10[ci]; p11[j] = g_P11[ci];
            vz[j]  = g_qz[ci];  vy[j]  = g_qy[ci];
        }
#pragma unroll
        for (int j = 0; j < 8; j++) {
            int ci = (b * NCH + g + j) * MM + m;
            g_iz[ci] = z; g_iy[ci] = y;
            float nz = p00[j]*z + p01[j]*y + vz[j];
            float ny = p10[j]*z + p11[j]*y + vy[j];
            z = nz; y = ny;
        }
    }
}

// ---------------- scan phase 3 (fused act): replay, write bf16 splits ------
__global__ void scan_phase3(const float* __restrict__ bo, const float* __restrict__ bz,
                            const float* __restrict__ bB)
{
    int b = blockIdx.y, ch = blockIdx.x, m = threadIdx.x;
    const float bom = bo[m], bzm = bz[m], bBz = bB[m], bBy = bB[64 + m];
    const size_t rt0 = (size_t)b * TT + ch * CHUNK;
    const float* Gp = g_G + rt0 * 256;
    int ci = (b * NCH + ch) * MM + m;
    float z = g_iz[ci], y = g_iy[ci];
#pragma unroll 4
    for (int s = 0; s < CHUNK; s++) {
        const float* Gr = Gp + (size_t)s * 256;
        float go = Gr[m], gz = Gr[64 + m];
        float Fz = Gr[128 + m] + bBz;
        float Fy = Gr[192 + m] + bBy;
        float a, bb, cc;
        coeffs(go, gz, bom, bzm, a, bb, cc);
        float nz = a*z - bb*y + Fz;
        float ny = cc*z + a*y + Fy;
        z = nz; y = ny;
        __nv_bfloat16 h, l;
        size_t xo = (rt0 + s) * KX;
        split2(z, h, l); g_Xh[xo + m] = h;      g_Xl[xo + m] = l;
        split2(y, h, l); g_Xh[xo + 64 + m] = h; g_Xl[xo + 64 + m] = l;
    }
}

// ---------------- launch ----------------
extern "C" void kernel_launch(void* const* d_in, const int* in_sizes, int n_in,
                              void* d_out, int out_size)
{
    const float* u   = (const float*)d_in[0];
    const float* Wo  = (const float*)d_in[1];
    const float* bo  = (const float*)d_in[2];
    const float* Wz  = (const float*)d_in[3];
    const float* bz  = (const float*)d_in[4];
    const float* WB  = (const float*)d_in[5];
    const float* bBv = (const float*)d_in[6];
    const float* Cm  = (const float*)d_in[7];
    const float* Dm  = (const float*)d_in[8];
    float* out = (float*)d_out;

    static int configured = 0;
    if (!configured) {
        cudaFuncSetAttribute(gemm_mma, cudaFuncAttributeMaxDynamicSharedMemorySize, GEMM_SMEM);
        configured = 1;
    }

    __nv_bfloat16 *Xh, *Xl, *Wph, *Wpl, *Wch, *Wcl; float* G;
    cudaGetSymbolAddress((void**)&Xh,  g_Xh);
    cudaGetSymbolAddress((void**)&Xl,  g_Xl);
    cudaGetSymbolAddress((void**)&Wph, g_Wph);
    cudaGetSymbolAddress((void**)&Wpl, g_Wpl);
    cudaGetSymbolAddress((void**)&Wch, g_Wch);
    cudaGetSymbolAddress((void**)&Wcl, g_Wcl);
    cudaGetSymbolAddress((void**)&G,   g_G);

    // 1. fp32 -> split bf16 conversions
    conv_u <<<(BT * 256 + 255) / 256, 256>>>(u);
    conv_wp<<<(256 * 256 + 255) / 256, 256>>>(Wo, Wz, WB);
    conv_wc<<<(1024 * 288 + 255) / 256, 256>>>(Cm, Dm);

    // 2. projection GEMM: G[BT,256] = u_splits (K=1024) @ Wp^T
    gemm_mma<<<dim3(256 / 128, BT / 128), 256, GEMM_SMEM>>>(
        Xh + 128, Xl + 128, KX, Wph, Wpl, DD, G, 256, DD);

    // 3. fused activation + chunked parallel scan
    scan_phase1<<<dim3(NCH, BB), MM>>>(bo, bz, bBv);
    scan_phase2<<<1, BB * MM>>>();
    scan_phase3<<<dim3(NCH, BB), MM>>>(bo, bz, bBv);

    // 4. output GEMM: out[BT,1024] = X (K=1152) @ [C|D]^T
    gemm_mma<<<dim3(DD / 128, BT / 128), 256, GEMM_SMEM>>>(
        Xh, Xl, KX, Wch, Wcl, KX, out, DD, KX);
}

// round 5
// speedup vs baseline: 3.2675x; 1.0125x over previous
#include <cuda_runtime.h>
#include <cuda_bf16.h>
#include <cstdint>
#include <math.h>

// ---------------- problem constants ----------------
#define BB   4
#define TT   4096
#define DD   1024
#define MM   64
#define NN   128
#define BT   (BB*TT)     // 16384
#define DT_C 0.01f
#define CHUNK 32
#define NCH  (TT/CHUNK)  // 128
#define KX   1152        // concat K for out gemm: [xs(128) | u(1024)]

// ---------------- portable PTX helpers (sm_80+ ISA only) ----------------
__device__ __forceinline__ uint32_t smem_to_u32(const void* p) {
    uint32_t a;
    asm("{ .reg .u64 t; cvta.to.shared.u64 t, %1; cvt.u32.u64 %0, t; }" : "=r"(a) : "l"(p));
    return a;
}
#define CP_ASYNC16(SM, GM) \
    asm volatile("cp.async.cg.shared.global [%0], [%1], 16;" :: "r"(SM), "l"(GM) : "memory")
#define CP_COMMIT() asm volatile("cp.async.commit_group;" ::: "memory")
#define CP_WAIT0()  asm volatile("cp.async.wait_group 0;" ::: "memory")
#define LDSM_X4(R0,R1,R2,R3, ADDR) \
    asm volatile("ldmatrix.sync.aligned.m8n8.x4.shared.b16 {%0,%1,%2,%3}, [%4];" \
        : "=r"(R0),"=r"(R1),"=r"(R2),"=r"(R3) : "r"(ADDR))
#define MMA_BF16(D, A, B) \
    asm volatile("mma.sync.aligned.m16n8k16.row.col.f32.bf16.bf16.f32 " \
        "{%0,%1,%2,%3}, {%4,%5,%6,%7}, {%8,%9}, {%0,%1,%2,%3};" \
        : "+f"((D)[0]), "+f"((D)[1]), "+f"((D)[2]), "+f"((D)[3]) \
        : "r"((A)[0]), "r"((A)[1]), "r"((A)[2]), "r"((A)[3]), "r"((B)[0]), "r"((B)[1]))

// ---------------- scratch (static device, no allocation) ----------------
__device__ __align__(16) __nv_bfloat16 g_Wph[256*DD];         // proj W hi [256,1024]
__device__ __align__(16) __nv_bfloat16 g_Wpl[256*DD];
__device__ __align__(16) __nv_bfloat16 g_Wch[(size_t)DD*KX];  // [C|D] hi [1024,1152]
__device__ __align__(16) __nv_bfloat16 g_Wcl[(size_t)DD*KX];
__device__ __align__(16) float g_G[(size_t)BT*256];           // proj result
__device__ __align__(16) float g_xs[(size_t)BT*NN];           // scan outputs fp32
__device__ float g_P00[BB*NCH*MM], g_P01[BB*NCH*MM], g_P10[BB*NCH*MM], g_P11[BB*NCH*MM];
__device__ float g_qz[BB*NCH*MM],  g_qy[BB*NCH*MM];
__device__ float g_iz[BB*NCH*MM],  g_iy[BB*NCH*MM];

__device__ __forceinline__ void split2(float x, __nv_bfloat16& h, __nv_bfloat16& l) {
    h = __float2bfloat16(x);
    l = __float2bfloat16(x - __bfloat162float(h));
}

__device__ __forceinline__ void coeffs(float go, float gz, float bom, float bzm,
                                       float& a, float& bb, float& cc)
{
    float vo = go + bom;
    float sp = fmaxf(vo, 0.f) + log1pf(expf(-fabsf(vo)));
    float omega = fminf(fmaxf(sp, 1e-4f), 100.0f);
    float vz = gz + bzm;
    float zeta = 1.f / (1.f + expf(-vz));
    float d = 1.f - zeta;
    float A = omega * omega;
    float S = 1.f / (1.f + DT_C * DT_C * A);
    a  = d * S;
    bb = d * DT_C * A * S;
    cc = d * DT_C * S;
}

// ---------------- weight conversion (both weight groups, one kernel) -------
__global__ void conv_w(const float* __restrict__ Wo, const float* __restrict__ Wz,
                       const float* __restrict__ WB, const float* __restrict__ Cm,
                       const float* __restrict__ Dm)
{
    int i = blockIdx.x * blockDim.x + threadIdx.x;
    union { __nv_bfloat16 b[4]; uint2 u2; } ph, pl;
    if (i < 256 * 256) {                         // proj weights: 65536 float4s
        int row = i >> 8, c4 = i & 255;
        const float* src = (row < 64)  ? (Wo + (size_t)row * DD)
                         : (row < 128) ? (Wz + (size_t)(row - 64) * DD)
                                       : (WB + (size_t)(row - 128) * DD);
        float4 v = *reinterpret_cast<const float4*>(src + c4 * 4);
        split2(v.x, ph.b[0], pl.b[0]); split2(v.y, ph.b[1], pl.b[1]);
        split2(v.z, ph.b[2], pl.b[2]); split2(v.w, ph.b[3], pl.b[3]);
        size_t o = (size_t)row * DD + c4 * 4;
        *reinterpret_cast<uint2*>(&g_Wph[o]) = ph.u2;
        *reinterpret_cast<uint2*>(&g_Wpl[o]) = pl.u2;
    } else {
        int j = i - 256 * 256;                   // out weights: 1024*288 float4s
        if (j >= 1024 * 288) return;
        int row = j / 288, c4 = j % 288;
        int k = c4 * 4;
        float4 v = (k < 128)
            ? *reinterpret_cast<const float4*>(&Cm[(size_t)row * NN + k])
            : *reinterpret_cast<const float4*>(&Dm[(size_t)row * DD + (k - 128)]);
        split2(v.x, ph.b[0], pl.b[0]); split2(v.y, ph.b[1], pl.b[1]);
        split2(v.z, ph.b[2], pl.b[2]); split2(v.w, ph.b[3], pl.b[3]);
        size_t o = (size_t)row * KX + k;
        *reinterpret_cast<uint2*>(&g_Wch[o]) = ph.u2;
        *reinterpret_cast<uint2*>(&g_Wcl[o]) = pl.u2;
    }
}

// ---------------- fused split-bf16 GEMM with on-the-fly A conversion -------
// C = Ah*Bh^T + Al*Bh^T + Ah*Bl^T, fp32 accum.
// A is fp32: cols [0,kSplit) from A1 (ld lda1), cols [kSplit,K) from A2 (ld lda2).
// B is precomputed split bf16 (Bh,Bl), [Nrows, K] row-major, ld = K.
// CTA tile 128x128, K-chunk 32, double-buffered cp.async.
#define TILEB   10240                 // 128 rows * 80B (32 bf16 + pad)
#define AF32B   16384                 // 128 rows * 32 fp32
// smem layout (byte offsets):
//   [0, 2*AF32B)                   : A fp32 staging, 2 stages
//   [2*AF32B, 2*AF32B+4*TILEB)     : Bh,Bl  x 2 stages (stage-major: s0{Bh,Bl}, s1{Bh,Bl})
//   [.. + 2*TILEB)                 : Ah, Al (single buffer)
#define S_BOFF   (2*AF32B)
#define S_AOFF   (S_BOFF + 4*TILEB)
#define GEMM_SMEM (S_AOFF + 2*TILEB) // 32768 + 40960 + 20480 = 94208

__global__ void __launch_bounds__(256, 2)
gemm_fused(const float* __restrict__ A1, int lda1,
           const float* __restrict__ A2, int lda2, int kSplit,
           const __nv_bfloat16* __restrict__ Bh, const __nv_bfloat16* __restrict__ Bl,
           float* __restrict__ Cout, int ldc, int K)
{
    extern __shared__ char smc[];
    const uint32_t sb = smem_to_u32(smc);
    const int tid = threadIdx.x;
    const int wid = tid >> 5, lane = tid & 31;
    const int warpM = wid & 3, warpN = wid >> 2;
    const int rowBase = blockIdx.y * 128;
    const int colBase = blockIdx.x * 128;

    // A fp32 cp.async mapping: 1024 16B-units; thread t does f = i*256+t, i<4
    // f -> row r = f>>3, q = f&7 (4-float unit)
    auto load_A = [&](int stage, int k0) {
        const float* Ap; int ld, kc;
        if (k0 < kSplit) { Ap = A1; ld = lda1; kc = k0; }
        else             { Ap = A2; ld = lda2; kc = k0 - kSplit; }
#pragma unroll
        for (int i = 0; i < 4; i++) {
            int f = i * 256 + tid;
            int r = f >> 3, q = f & 7;
            uint32_t so = sb + stage * AF32B + f * 16;
            const float* g = Ap + (size_t)(rowBase + r) * ld + kc + q * 4;
            CP_ASYNC16(so, g);
        }
    };
    // B cp.async: 2 tiles x 128 rows x 4 units = 1024 units
    auto load_B = [&](int stage, int k0) {
#pragma unroll
        for (int i = 0; i < 4; i++) {
            int idx = i * 256 + tid;
            int tile = idx >> 9;               // 0=Bh, 1=Bl
            int e = idx & 511;
            int r = e >> 2, j = e & 3;
            uint32_t so = sb + S_BOFF + stage * 2 * TILEB + tile * TILEB + r * 80 + j * 16;
            const __nv_bfloat16* g = (tile ? Bl : Bh)
                + (size_t)(colBase + r) * K + k0 + j * 8;
            CP_ASYNC16(so, g);
        }
    };

    float acc[2][8][4];
#pragma unroll
    for (int a = 0; a < 2; a++)
#pragma unroll
        for (int b = 0; b < 8; b++)
#pragma unroll
            for (int c = 0; c < 4; c++) acc[a][b][c] = 0.f;

    const uint32_t aRowOff = (uint32_t)(lane & 15) * 80 + (uint32_t)(lane >> 4) * 16;
    const uint32_t bRowOff = (uint32_t)((lane & 7) + ((lane >> 4) & 1) * 8) * 80
                           + (uint32_t)((lane >> 3) & 1) * 16;

    const int nch = K / 32;
    load_A(0, 0); load_B(0, 0); CP_COMMIT();

    for (int c = 0; c < nch; c++) {
        CP_WAIT0();
        __syncthreads();                         // stage c data visible; compute c-1 done
        if (c + 1 < nch) {
            load_A((c + 1) & 1, (c + 1) * 32);
            load_B((c + 1) & 1, (c + 1) * 32);
            CP_COMMIT();
        }
        // convert A fp32 stage -> Ah/Al bf16 (each thread converts what it loaded)
        {
            const uint32_t src = sb + (c & 1) * AF32B;
#pragma unroll
            for (int i = 0; i < 4; i++) {
                int f = i * 256 + tid;
                int r = f >> 3, q = f & 7;
                float4 v = *reinterpret_cast<const float4*>(smc + (c & 1) * AF32B + f * 16);
                union { __nv_bfloat16 b[4]; uint2 u2; } ph, pl;
                split2(v.x, ph.b[0], pl.b[0]); split2(v.y, ph.b[1], pl.b[1]);
                split2(v.z, ph.b[2], pl.b[2]); split2(v.w, ph.b[3], pl.b[3]);
                uint32_t dst = r * 80 + q * 8;
                *reinterpret_cast<uint2*>(smc + S_AOFF + dst)         = ph.u2;
                *reinterpret_cast<uint2*>(smc + S_AOFF + TILEB + dst) = pl.u2;
            }
            (void)src;
        }
        __syncthreads();                         // Ah/Al ready
        // compute chunk c
        const uint32_t stB = sb + S_BOFF + (c & 1) * 2 * TILEB;
        const uint32_t stA = sb + S_AOFF;
#pragma unroll
        for (int k16 = 0; k16 < 2; k16++) {
            const uint32_t kb = (uint32_t)k16 * 32;
            uint32_t ah[2][4], al[2][4];
#pragma unroll
            for (int mf = 0; mf < 2; mf++) {
                uint32_t base = stA + (uint32_t)(warpM * 32 + mf * 16) * 80 + kb + aRowOff;
                LDSM_X4(ah[mf][0], ah[mf][1], ah[mf][2], ah[mf][3], base);
                LDSM_X4(al[mf][0], al[mf][1], al[mf][2], al[mf][3], base + TILEB);
            }
#pragma unroll
            for (int p = 0; p < 4; p++) {
                uint32_t base = stB + (uint32_t)(warpN * 64 + p * 16) * 80 + kb + bRowOff;
                uint32_t bh[2][2], bl[2][2];
                uint32_t r0, r1, r2, r3;
                LDSM_X4(r0, r1, r2, r3, base);
                bh[0][0] = r0; bh[0][1] = r1; bh[1][0] = r2; bh[1][1] = r3;
                LDSM_X4(r0, r1, r2, r3, base + TILEB);
                bl[0][0] = r0; bl[0][1] = r1; bl[1][0] = r2; bl[1][1] = r3;
#pragma unroll
                for (int h = 0; h < 2; h++) {
                    int nf = 2 * p + h;
#pragma unroll
                    for (int mf = 0; mf < 2; mf++) {
                        MMA_BF16(acc[mf][nf], ah[mf], bh[h]);
                        MMA_BF16(acc[mf][nf], al[mf], bh[h]);
                        MMA_BF16(acc[mf][nf], ah[mf], bl[h]);
                    }
                }
            }
        }
    }

    const int row0 = rowBase + warpM * 32 + (lane >> 2);
    const int col0 = colBase + warpN * 64 + (lane & 3) * 2;
#pragma unroll
    for (int mf = 0; mf < 2; mf++)
#pragma unroll
        for (int nf = 0; nf < 8; nf++) {
            int r = row0 + mf * 16, cc = col0 + nf * 8;
            float2 v0 = make_float2(acc[mf][nf][0], acc[mf][nf][1]);
            float2 v1 = make_float2(acc[mf][nf][2], acc[mf][nf][3]);
            *reinterpret_cast<float2*>(&Cout[(size_t)r * ldc + cc]) = v0;
            *reinterpret_cast<float2*>(&Cout[(size_t)(r + 8) * ldc + cc]) = v1;
        }
}

// ---------------- scan phase 1 (fused act): chunk summaries ----------------
__global__ void scan_phase1(const float* __restrict__ bo, const float* __restrict__ bz,
                            const float* __restrict__ bB)
{
    int b = blockIdx.y, ch = blockIdx.x, m = threadIdx.x;
    const float bom = bo[m], bzm = bz[m], bBz = bB[m], bBy = bB[64 + m];
    const float* Gp = g_G + ((size_t)b * TT + ch * CHUNK) * 256;
    float P00 = 1.f, P01 = 0.f, P10 = 0.f, P11 = 1.f, qz = 0.f, qy = 0.f;
#pragma unroll 4
    for (int s = 0; s < CHUNK; s++) {
        const float* Gr = Gp + (size_t)s * 256;
        float go = Gr[m], gz = Gr[64 + m];
        float Fz = Gr[128 + m] + bBz;
        float Fy = Gr[192 + m] + bBy;
        float a, bb, cc;
        coeffs(go, gz, bom, bzm, a, bb, cc);
        float n00 = a*P00 - bb*P10, n01 = a*P01 - bb*P11;
        float n10 = cc*P00 + a*P10, n11 = cc*P01 + a*P11;
        float nqz = a*qz - bb*qy + Fz;
        float nqy = cc*qz + a*qy + Fy;
        P00=n00; P01=n01; P10=n10; P11=n11; qz=nqz; qy=nqy;
    }
    int ci = (b * NCH + ch) * MM + m;
    g_P00[ci]=P00; g_P01[ci]=P01; g_P10[ci]=P10; g_P11[ci]=P11;
    g_qz[ci]=qz;   g_qy[ci]=qy;
}

// ---------------- scan phase 2: combine (batched prefetch) ----------------
__global__ void scan_phase2()
{
    int tid = threadIdx.x;        // 256 = B*M
    int b = tid >> 6, m = tid & 63;
    float z = 0.f, y = 0.f;
    for (int g = 0; g < NCH; g += 8) {
        float p00[8], p01[8], p10[8], p11[8], vz[8], vy[8];
#pragma unroll
        for (int j = 0; j < 8; j++) {
            int ci = (b * NCH + g + j) * MM + m;
            p00[j] = g_P00[ci]; p01[j] = g_P01[ci];
            p10[j] = g_P10[ci]; p11[j] = g_P11[ci];
            vz[j]  = g_qz[ci];  vy[j]  = g_qy[ci];
        }
#pragma unroll
        for (int j = 0; j < 8; j++) {
            int ci = (b * NCH + g + j) * MM + m;
            g_iz[ci] = z; g_iy[ci] = y;
            float nz = p00[j]*z + p01[j]*y + vz[j];
            float ny = p10[j]*z + p11[j]*y + vy[j];
            z = nz; y = ny;
        }
    }
}

// ---------------- scan phase 3 (fused act): replay, write fp32 xs ----------
__global__ void scan_phase3(const float* __restrict__ bo, const float* __restrict__ bz,
                            const float* __restrict__ bB)
{
    int b = blockIdx.y, ch = blockIdx.x, m = threadIdx.x;
    const float bom = bo[m], bzm = bz[m], bBz = bB[m], bBy = bB[64 + m];
    const size_t rt0 = (size_t)b * TT + ch * CHUNK;
    const float* Gp = g_G + rt0 * 256;
    int ci = (b * NCH + ch) * MM + m;
    float z = g_iz[ci], y = g_iy[ci];
#pragma unroll 4
    for (int s = 0; s < CHUNK; s++) {
        const float* Gr = Gp + (size_t)s * 256;
        float go = Gr[m], gz = Gr[64 + m];
        float Fz = Gr[128 + m] + bBz;
        float Fy = Gr[192 + m] + bBy;
        float a, bb, cc;
        coeffs(go, gz, bom, bzm, a, bb, cc);
        float nz = a*z - bb*y + Fz;
        float ny = cc*z + a*y + Fy;
        z = nz; y = ny;
        size_t xo = (rt0 + s) * NN;
        g_xs[xo + m]      = z;
        g_xs[xo + 64 + m] = y;
    }
}

// ---------------- launch ----------------
extern "C" void kernel_launch(void* const* d_in, const int* in_sizes, int n_in,
                              void* d_out, int out_size)
{
    const float* u   = (const float*)d_in[0];
    const float* Wo  = (const float*)d_in[1];
    const float* bo  = (const float*)d_in[2];
    const float* Wz  = (const float*)d_in[3];
    const float* bz  = (const float*)d_in[4];
    const float* WB  = (const float*)d_in[5];
    const float* bBv = (const float*)d_in[6];
    const float* Cm  = (const float*)d_in[7];
    const float* Dm  = (const float*)d_in[8];
    float* out = (float*)d_out;

    static int configured = 0;
    if (!configured) {
        cudaFuncSetAttribute(gemm_fused, cudaFuncAttributeMaxDynamicSharedMemorySize, GEMM_SMEM);
        configured = 1;
    }

    __nv_bfloat16 *Wph, *Wpl, *Wch, *Wcl; float *G, *Xs;
    cudaGetSymbolAddress((void**)&Wph, g_Wph);
    cudaGetSymbolAddress((void**)&Wpl, g_Wpl);
    cudaGetSymbolAddress((void**)&Wch, g_Wch);
    cudaGetSymbolAddress((void**)&Wcl, g_Wcl);
    cudaGetSymbolAddress((void**)&G,   g_G);
    cudaGetSymbolAddress((void**)&Xs,  g_xs);

    // 1. weight split conversion (one kernel)
    conv_w<<<(256*256 + 1024*288 + 255) / 256, 256>>>(Wo, Wz, WB, Cm, Dm);

    // 2. projection GEMM: G[BT,256] = u(fp32, on-the-fly split) @ Wp^T
    gemm_fused<<<dim3(256 / 128, BT / 128), 256, GEMM_SMEM>>>(
        u, DD, u, DD, /*kSplit=*/2048, Wph, Wpl, G, 256, DD);

    // 3. fused activation + chunked parallel scan
    scan_phase1<<<dim3(NCH, BB), MM>>>(bo, bz, bBv);
    scan_phase2<<<1, BB * MM>>>();
    scan_phase3<<<dim3(NCH, BB), MM>>>(bo, bz, bBv);

    // 4. output GEMM: out[BT,1024] = [xs | u](fp32, on-the-fly split) @ [C|D]^T
    gemm_fused<<<dim3(DD / 128, BT / 128), 256, GEMM_SMEM>>>(
        Xs, NN, u, DD, /*kSplit=*/128, Wch, Wcl, out, DD, KX);
}